// round 1
// baseline (speedup 1.0000x reference)
#include <cuda_runtime.h>
#include <cstdint>

// Scratch: per-(b,c) squeeze means and excitation scales. 32*512 = 16384.
__device__ float d_sq[16384];
__device__ float d_e[16384];

// ---------------------------------------------------------------------------
// Kernel 1: squeeze = mean over 56*56 = 3136 spatial elements per (b,c).
// One block per (b,c). 3136 floats = 784 float4. 128 threads -> ~6 iters.
// ---------------------------------------------------------------------------
__global__ __launch_bounds__(128) void se_reduce(const float* __restrict__ x) {
    const int bc = blockIdx.x;
    const float4* __restrict__ p =
        reinterpret_cast<const float4*>(x) + (size_t)bc * 784;

    float s = 0.0f;
    #pragma unroll
    for (int i = threadIdx.x; i < 784; i += 128) {
        float4 v = p[i];
        s += (v.x + v.y) + (v.z + v.w);
    }

    // warp reduce
    #pragma unroll
    for (int off = 16; off > 0; off >>= 1)
        s += __shfl_down_sync(0xFFFFFFFFu, s, off);

    __shared__ float warp_sums[4];
    const int lane = threadIdx.x & 31;
    const int wid  = threadIdx.x >> 5;
    if (lane == 0) warp_sums[wid] = s;
    __syncthreads();

    if (threadIdx.x == 0) {
        float tot = warp_sums[0] + warp_sums[1] + warp_sums[2] + warp_sums[3];
        d_sq[bc] = tot * (1.0f / 3136.0f);
    }
}

// ---------------------------------------------------------------------------
// Kernel 2: excitation. One block per batch, 512 threads.
//   hid[j] = relu(sum_k sq[k] * w1[j,k] + b1[j])        j in [0,32)
//   e[c]   = sigmoid(sum_j hid[j] * w2[c,j] + b2[c])    c in [0,512)
// ---------------------------------------------------------------------------
__global__ __launch_bounds__(512) void se_excite(const float* __restrict__ w1,
                                                 const float* __restrict__ b1,
                                                 const float* __restrict__ w2,
                                                 const float* __restrict__ b2) {
    const int b = blockIdx.x;
    const int t = threadIdx.x;

    __shared__ float sq[512];
    __shared__ float hid[32];

    sq[t] = d_sq[b * 512 + t];
    __syncthreads();

    if (t < 32) {
        float acc = b1[t];
        const float* __restrict__ wrow = w1 + t * 512;
        #pragma unroll 8
        for (int k = 0; k < 512; ++k)
            acc = fmaf(sq[k], wrow[k], acc);
        hid[t] = fmaxf(acc, 0.0f);
    }
    __syncthreads();

    float acc = b2[t];
    const float* __restrict__ w2row = w2 + t * 32;
    #pragma unroll
    for (int j = 0; j < 32; ++j)
        acc = fmaf(hid[j], w2row[j], acc);

    d_e[b * 512 + t] = 1.0f / (1.0f + __expf(-acc));
}

// ---------------------------------------------------------------------------
// Kernel 3: out = x * e[b,c]. One float4 per thread.
// Total float4 count: 32*512*784 = 12,845,056. bc = idx / 784.
// ---------------------------------------------------------------------------
__global__ __launch_bounds__(256) void se_scale(const float* __restrict__ x,
                                                float* __restrict__ out) {
    const unsigned int i = blockIdx.x * 256u + threadIdx.x;
    const unsigned int bc = i / 784u;
    const float e = __ldg(&d_e[bc]);

    float4 v = reinterpret_cast<const float4*>(x)[i];
    v.x *= e; v.y *= e; v.z *= e; v.w *= e;
    reinterpret_cast<float4*>(out)[i] = v;
}

// ---------------------------------------------------------------------------
// Launcher
// ---------------------------------------------------------------------------
extern "C" void kernel_launch(void* const* d_in, const int* in_sizes, int n_in,
                              void* d_out, int out_size) {
    const float* x  = (const float*)d_in[0];
    const float* w1 = (const float*)d_in[1];
    const float* b1 = (const float*)d_in[2];
    const float* w2 = (const float*)d_in[3];
    const float* b2 = (const float*)d_in[4];
    float* out = (float*)d_out;

    // 32 * 512 = 16384 (b,c) slices
    se_reduce<<<16384, 128>>>(x);
    se_excite<<<32, 512>>>(w1, b1, w2, b2);
    // 12,845,056 float4 / 256 threads = 50176 blocks
    se_scale<<<50176, 256>>>(x, out);
}

// round 2
// speedup vs baseline: 1.3336x; 1.3336x over previous
#include <cuda_runtime.h>
#include <cstdint>

// Scratch: per-(b,c) squeeze means and excitation scales. 32*512 = 16384.
__device__ float d_sq[16384];
__device__ float d_e[16384];

// ---------------------------------------------------------------------------
// Kernel 1: squeeze = mean over 56*56 = 3136 spatial elements per (b,c).
// One block per (b,c). 784 float4 per slice, 128 threads. Ascending order so
// the TAIL of x is L2-resident when se_scale (reversed) starts.
// ---------------------------------------------------------------------------
__global__ __launch_bounds__(128) void se_reduce(const float* __restrict__ x) {
    const int bc = blockIdx.x;
    const float4* __restrict__ p =
        reinterpret_cast<const float4*>(x) + (size_t)bc * 784;

    float s = 0.0f;
    #pragma unroll
    for (int i = threadIdx.x; i < 784; i += 128) {
        float4 v = p[i];
        s += (v.x + v.y) + (v.z + v.w);
    }

    #pragma unroll
    for (int off = 16; off > 0; off >>= 1)
        s += __shfl_down_sync(0xFFFFFFFFu, s, off);

    __shared__ float warp_sums[4];
    const int lane = threadIdx.x & 31;
    const int wid  = threadIdx.x >> 5;
    if (lane == 0) warp_sums[wid] = s;
    __syncthreads();

    if (threadIdx.x == 0) {
        float tot = warp_sums[0] + warp_sums[1] + warp_sums[2] + warp_sums[3];
        d_sq[bc] = tot * (1.0f / 3136.0f);
    }
}

// ---------------------------------------------------------------------------
// Kernel 2: excitation. One block per batch, 1024 threads.
// Phase 1: warp j computes hid[j] = relu(sq . w1[j,:] + b1[j]) via 16 FMAs
//          per lane + shuffle reduce (kills the 512-deep dependent chain).
// Phase 2: threads 0..511 compute e[c] = sigmoid(hid . w2[c,:] + b2[c]).
// ---------------------------------------------------------------------------
__global__ __launch_bounds__(1024) void se_excite(const float* __restrict__ w1,
                                                  const float* __restrict__ b1,
                                                  const float* __restrict__ w2,
                                                  const float* __restrict__ b2) {
    const int b    = blockIdx.x;
    const int t    = threadIdx.x;
    const int wid  = t >> 5;
    const int lane = t & 31;

    __shared__ float sq[512];
    __shared__ float hid[32];

    if (t < 512) sq[t] = d_sq[b * 512 + t];
    __syncthreads();

    // warp `wid` computes hidden unit `wid`
    {
        const float* __restrict__ wrow = w1 + wid * 512;
        float acc = 0.0f;
        #pragma unroll
        for (int k = 0; k < 16; ++k) {
            int idx = lane + 32 * k;
            acc = fmaf(sq[idx], wrow[idx], acc);
        }
        #pragma unroll
        for (int off = 16; off > 0; off >>= 1)
            acc += __shfl_down_sync(0xFFFFFFFFu, acc, off);
        if (lane == 0) hid[wid] = fmaxf(acc + b1[wid], 0.0f);
    }
    __syncthreads();

    if (t < 512) {
        float acc = b2[t];
        const float* __restrict__ w2row = w2 + t * 32;
        #pragma unroll
        for (int j = 0; j < 32; ++j)
            acc = fmaf(hid[j], w2row[j], acc);
        d_e[b * 512 + t] = 1.0f / (1.0f + __expf(-acc));
    }
}

// ---------------------------------------------------------------------------
// Kernel 3: out = x * e[b,c].
// 4 float4 (64B) per thread, loads batched before stores (MLP=4).
// Blocks run in REVERSED order: the first wave touches the tail of x, which
// se_reduce just left resident in L2 (~120MB) -> those reads skip DRAM.
// Streaming hints: x second-read and out stores are evict-first so they
// don't flush the useful L2 contents.
// Total float4 = 32*512*784 = 12,845,056 = 12544 blocks * 1024.
// ---------------------------------------------------------------------------
__global__ __launch_bounds__(256) void se_scale(const float* __restrict__ x,
                                                float* __restrict__ out) {
    const unsigned int blk  = gridDim.x - 1u - blockIdx.x;   // reversed
    const unsigned int base = blk * 1024u + threadIdx.x;

    const float4* __restrict__ x4 = reinterpret_cast<const float4*>(x);
    float4* __restrict__ o4       = reinterpret_cast<float4*>(out);

    float4 v[4];
    float  e[4];

    #pragma unroll
    for (int j = 0; j < 4; ++j)
        v[j] = __ldcs(x4 + (base + j * 256u));

    #pragma unroll
    for (int j = 0; j < 4; ++j)
        e[j] = __ldg(&d_e[(base + j * 256u) / 784u]);

    #pragma unroll
    for (int j = 0; j < 4; ++j) {
        float4 r = v[j];
        const float s = e[j];
        r.x *= s; r.y *= s; r.z *= s; r.w *= s;
        __stcs(o4 + (base + j * 256u), r);
    }
}

// ---------------------------------------------------------------------------
// Launcher
// ---------------------------------------------------------------------------
extern "C" void kernel_launch(void* const* d_in, const int* in_sizes, int n_in,
                              void* d_out, int out_size) {
    const float* x  = (const float*)d_in[0];
    const float* w1 = (const float*)d_in[1];
    const float* b1 = (const float*)d_in[2];
    const float* w2 = (const float*)d_in[3];
    const float* b2 = (const float*)d_in[4];
    float* out = (float*)d_out;

    se_reduce<<<16384, 128>>>(x);
    se_excite<<<32, 1024>>>(w1, b1, w2, b2);
    se_scale<<<12544, 256>>>(x, out);
}